// round 15
// baseline (speedup 1.0000x reference)
#include <cuda_runtime.h>
#include <cuda_fp16.h>
#include <cstdint>

#define BATCH 8
#define NT    1024
typedef unsigned long long ull;
typedef unsigned int u32;

// ---------------- scratch (__device__ globals; no allocation allowed) ------
__device__ __align__(16) float g_bufB[BATCH * NT * 64];      // layer3 f32 out
// features pre-split to fp16 hi/lo planes [b][node][fs]
__device__ __align__(16) __half g_xhi[BATCH * NT * 256];
__device__ __align__(16) __half g_xlo[BATCH * NT * 256];
// fp16 weights (single plane)
__device__ __align__(16) __half g_w1h[256 * 64];
__device__ __align__(16) __half g_w2h[256 * 256];
__device__ __align__(16) __half g_w3h[64 * 256];
// packed source scores (s, Es, Es2, 0) and dest scores (d, Ed, Ed2, 0), [h][b][node]
__device__ __align__(16) float4 g_spk[4 * BATCH * NT];
__device__ __align__(16) float4 g_dpk[4 * BATCH * NT];
// pre-transposed fp16 features [h][b][c=64][node=1024]
__device__ __align__(16) __half g_hT[4 * BATCH * 64 * NT];
__device__ __align__(16) u32   g_bits[BATCH * NT * (NT / 32)];
__device__ __align__(16) float g_gsum[BATCH * 64];
__device__ __align__(16) float g_z2[BATCH];

// ---------------- helpers --------------------------------------------------
__device__ __forceinline__ uint32_t smem_u32(const void* p) {
    uint32_t a;
    asm("{ .reg .u64 t; cvta.to.shared.u64 t, %1; cvt.u32.u64 %0, t; }" : "=r"(a) : "l"(p));
    return a;
}

__device__ __forceinline__ void ldsm4(u32* r, u32 addr) {
    asm volatile("ldmatrix.sync.aligned.m8n8.x4.shared.b16 {%0,%1,%2,%3}, [%4];"
                 : "=r"(r[0]), "=r"(r[1]), "=r"(r[2]), "=r"(r[3]) : "r"(addr));
}

__device__ __forceinline__ void mmaf16(float* c, const u32* a, u32 b0, u32 b1) {
    asm volatile(
        "mma.sync.aligned.m16n8k16.row.col.f32.f16.f16.f32 "
        "{%0,%1,%2,%3}, {%4,%5,%6,%7}, {%8,%9}, {%0,%1,%2,%3};"
        : "+f"(c[0]), "+f"(c[1]), "+f"(c[2]), "+f"(c[3])
        : "r"(a[0]), "r"(a[1]), "r"(a[2]), "r"(a[3]), "r"(b0), "r"(b1));
}

// e_ij = adjbit * ( s_j + d_i > 0 ? Es_j*Ed_i : Es2_j*Ed2_i )
__device__ __forceinline__ float edgef(float4 p, float4 dp, u32 bit) {
    float e = (p.x + dp.x > 0.f) ? p.y * dp.y : p.z * dp.z;
    return bit ? e : 0.f;
}

// pack two fp32 into f16x2 (lower = ex, upper = ey) in one cvt
__device__ __forceinline__ u32 packh2(float ex, float ey) {
    u32 r;
    asm("cvt.rn.f16x2.f32 %0, %1, %2;" : "=r"(r) : "f"(ey), "f"(ex));
    return r;
}

// fp16 hi/lo split of a pair, packed
__device__ __forceinline__ void split2h(float x0, float x1, u32& hi, u32& lo) {
    hi = packh2(x0, x1);
    __half2 hv = *(__half2*)&hi;
    float2 bk = __half22float2(hv);
    lo = packh2(x0 - bk.x, x1 - bk.y);
}

__device__ __forceinline__ u32 swzf(u32 off) { return off ^ ((off >> 3) & 0x70); }

__device__ __forceinline__ void cpasync16(u32 dst, const void* src) {
    asm volatile("cp.async.cg.shared.global [%0], [%1], 16;" :: "r"(dst), "l"(src) : "memory");
}
#define CP_COMMIT() asm volatile("cp.async.commit_group;" ::: "memory")
#define CP_WAIT0()  asm volatile("cp.async.wait_group 0;" ::: "memory")

#define ONESH 0x3C003C00u   // two fp16 1.0

// ---------------- adj bit packing (with self loops) ------------------------
// 256 threads = 8 warps; warp handles one row. grid = M/8.
__global__ __launch_bounds__(256) void pack_adj_kernel(
    const int* __restrict__ adj, u32* __restrict__ bits)
{
    int row = blockIdx.x * 8 + (threadIdx.x >> 5);
    int lane = threadIdx.x & 31;
    int i = row & (NT - 1);
    const int* arow = adj + (size_t)row * NT;
#pragma unroll 8
    for (int w = 0; w < 32; w++) {
        int j = w * 32 + lane;
        unsigned m = __ballot_sync(0xffffffffu, (arow[j] > 0) || (j == i));
        if (lane == 0) bits[row * 32 + w] = m;
    }
}

// ---------------- f32 -> fp16 conversions ----------------------------------
__global__ void convh_kernel(const float* __restrict__ src, __half* __restrict__ dst, int n4) {
    int i = blockIdx.x * 256 + threadIdx.x;
    if (i >= n4) return;
    float4 v = *(const float4*)(src + i * 4);
    uint2 o;
    o.x = packh2(v.x, v.y);
    o.y = packh2(v.z, v.w);
    *(uint2*)(dst + i * 4) = o;
}

__global__ void xsplit_kernel(const float* __restrict__ src,
                              __half* __restrict__ hi, __half* __restrict__ lo, int n4) {
    int i = blockIdx.x * 256 + threadIdx.x;
    if (i >= n4) return;
    float4 v = *(const float4*)(src + i * 4);
    u32 h0, h1, l0, l1;
    split2h(v.x, v.y, h0, l0);
    split2h(v.z, v.w, h1, l1);
    *(uint2*)(hi + i * 4) = make_uint2(h0, h1);
    *(uint2*)(lo + i * 4) = make_uint2(l0, l1);
}

// ---------------- GEMM: all-fp16 operands, cp.async pipeline ---------------
// X pre-split hi/lo planes [b][node][K], W pre-converted fp16. 2 MMA passes.
// Epilogue: attention scores + fp16 transposed feature write.
#define TPAD 136
#define GH_BUF   40960                      // Xh 16K + Xl 16K + W 8K
#define GH_SMEM  (2 * GH_BUF)
__global__ __launch_bounds__(256) void gemm_h16(
    const __half* __restrict__ Xh, const __half* __restrict__ Xl,
    const __half* __restrict__ Wh,
    const float* __restrict__ a_src, const float* __restrict__ a_dst,
    float4* __restrict__ spk, float4* __restrict__ dpk,
    __half* __restrict__ hT, int K)
{
    extern __shared__ __align__(128) char smem[];
    const u32 sb = smem_u32(smem);

    const int tid = threadIdx.x;
    const int w = tid >> 5, l = tid & 31;
    const int h = blockIdx.y;
    const int m0 = blockIdx.x * 128, n0 = h * 64;

    float acc[8][4];
#pragma unroll
    for (int ng = 0; ng < 8; ng++)
#pragma unroll
        for (int r = 0; r < 4; r++) acc[ng][r] = 0.f;

    const int arow = w * 16 + (l & 7) + ((l >> 3) & 1) * 8;
    const int akh  = (l >> 4);
    const int sub = l >> 3;
    const int brow = (l & 7) + ((sub >> 1) << 3);

    const int nIter = K / 64;

    auto issue = [&](int t) {
        int k0 = t * 64;
        u32 base = sb + (t & 1) * GH_BUF;
#pragma unroll
        for (int i = 0; i < 4; i++) {
            int c = tid + i * 256;
            int row = c >> 3, kg = c & 7;
            u32 off = swzf((u32)(row * 128 + kg * 16));
            cpasync16(base + off,         Xh + (size_t)(m0 + row) * K + k0 + kg * 8);
            cpasync16(base + 16384 + off, Xl + (size_t)(m0 + row) * K + k0 + kg * 8);
        }
#pragma unroll
        for (int i = 0; i < 2; i++) {
            int c = tid + i * 256;
            int row = c >> 3, kg = c & 7;
            u32 off = swzf((u32)(row * 128 + kg * 16));
            cpasync16(base + 32768 + off, Wh + (size_t)(n0 + row) * K + k0 + kg * 8);
        }
        CP_COMMIT();
    };

    issue(0);

    for (int t = 0; t < nIter; t++) {
        CP_WAIT0();
        __syncthreads();
        if (t + 1 < nIter) issue(t + 1);

        u32 base = sb + (t & 1) * GH_BUF;
#pragma unroll
        for (int q = 0; q < 4; q++) {
            u32 ah[4], al[4];
            u32 aoff = swzf((u32)(arow * 128 + q * 32 + akh * 16));
            ldsm4(ah, base + aoff);
            ldsm4(al, base + 16384 + aoff);
            const int bchunk = 2 * q + (sub & 1);
            u32 bh[16];
#pragma unroll
            for (int g = 0; g < 4; g++) {
                u32 off = swzf((u32)((g * 16 + brow) * 128 + bchunk * 16));
                ldsm4(bh + g * 4, base + 32768 + off);
            }
#pragma unroll
            for (int g = 0; g < 4; g++) {
#pragma unroll
                for (int m = 0; m < 2; m++) {
                    int ng = g * 2 + m;
                    u32 b0 = bh[g * 4 + 2 * m], b1 = bh[g * 4 + 2 * m + 1];
                    mmaf16(acc[ng], ah, b0, b1);
                    mmaf16(acc[ng], al, b0, b1);
                }
            }
        }
        __syncthreads();
    }

    const int r0 = w * 16 + (l >> 2);
    const int r1 = r0 + 8;

    // ---- epilogue 1: attention scores ----
    {
        float s0 = 0.f, d0 = 0.f, s1 = 0.f, d1 = 0.f;
#pragma unroll
        for (int ng = 0; ng < 8; ng++) {
            int col = ng * 8 + 2 * (l & 3);
            float2 av = *(const float2*)(a_src + n0 + col);
            float2 dv = *(const float2*)(a_dst + n0 + col);
            s0 += acc[ng][0] * av.x + acc[ng][1] * av.y;
            d0 += acc[ng][0] * dv.x + acc[ng][1] * dv.y;
            s1 += acc[ng][2] * av.x + acc[ng][3] * av.y;
            d1 += acc[ng][2] * dv.x + acc[ng][3] * dv.y;
        }
        s0 += __shfl_xor_sync(0xffffffffu, s0, 1);
        s0 += __shfl_xor_sync(0xffffffffu, s0, 2);
        d0 += __shfl_xor_sync(0xffffffffu, d0, 1);
        d0 += __shfl_xor_sync(0xffffffffu, d0, 2);
        s1 += __shfl_xor_sync(0xffffffffu, s1, 1);
        s1 += __shfl_xor_sync(0xffffffffu, s1, 2);
        d1 += __shfl_xor_sync(0xffffffffu, d1, 1);
        d1 += __shfl_xor_sync(0xffffffffu, d1, 2);
        if ((l & 3) == 0) {
            int idx0 = h * (BATCH * NT) + m0 + r0;
            int idx1 = h * (BATCH * NT) + m0 + r1;
            spk[idx0] = make_float4(s0, __expf(s0), __expf(0.2f * s0), 0.f);
            dpk[idx0] = make_float4(d0, __expf(d0), __expf(0.2f * d0), 0.f);
            spk[idx1] = make_float4(s1, __expf(s1), __expf(0.2f * s1), 0.f);
            dpk[idx1] = make_float4(d1, __expf(d1), __expf(0.2f * d1), 0.f);
        }
    }

    // ---- epilogue 2: fp16 transpose via smem bounce ----
    __syncthreads();
    unsigned short* Th = (unsigned short*)smem;
#pragma unroll
    for (int ng = 0; ng < 8; ng++) {
        int col = ng * 8 + 2 * (l & 3);
#pragma unroll
        for (int v = 0; v < 4; v++) {
            int cc = col + (v & 1);
            int node = (v < 2) ? r0 : r1;
            u32 p = packh2(acc[ng][v], 0.f);
            Th[cc * TPAD + node] = (unsigned short)(p & 0xffffu);
        }
    }
    __syncthreads();

    const int b = m0 >> 10;
    const int node0 = m0 & (NT - 1);
    const size_t gbase = ((size_t)((h * BATCH + b) * 64)) * NT + node0;
    {
        int c = tid >> 2;
#pragma unroll
        for (int i = 0; i < 4; i++) {
            int nch = (tid & 3) + 4 * i;
            uint4 vh = *(const uint4*)(Th + c * TPAD + nch * 8);
            *(uint4*)(hT + gbase + (size_t)c * NT + nch * 8) = vh;
        }
    }
}

// ---------------- HMMA aggregation (fp16 single-pass) ----------------------
// Epilogue writes either f32 (layer 3, for readout) or pre-split fp16 hi/lo
// planes (layers 1-2, consumed by gemm_h16's cp.async staging).
__global__ __launch_bounds__(256, 2) void agg_mma_kernel(
    const __half* __restrict__ hTA,
    const float4* __restrict__ spkA, const float4* __restrict__ dpkA,
    const ull* __restrict__ bits64,
    const float* __restrict__ bias,
    __half* __restrict__ xhi, __half* __restrict__ xlo,
    float* __restrict__ xoutf, int wf32, int H)
{
    __shared__ __align__(16) __half sh_h[2][64 * 64];
    __shared__ __align__(16) float4 sh_sp[2][64];

    const int tid = threadIdx.x;
    const int w = tid >> 5, l = tid & 31;
    const int b = blockIdx.z, h = blockIdx.y;
    const int i0 = blockIdx.x * 128;
    const int hb = h * BATCH + b;
    const int fs = H * 64;

    const int r0 = w * 16 + (l >> 2);
    const int r1 = r0 + 8;
    const float4 dp0 = dpkA[hb * NT + i0 + r0];
    const float4 dp1 = dpkA[hb * NT + i0 + r1];
    const ull* mrow0 = bits64 + (size_t)(b * NT + i0 + r0) * 16;
    const ull* mrow1 = bits64 + (size_t)(b * NT + i0 + r1) * 16;

    const float4* spkp = spkA + hb * NT;
    const __half* hhp = hTA + (size_t)hb * 64 * NT;

    const int c0 = tid >> 3, jc = tid & 7;
    const u32 st0 = swzf((u32)(c0 * 128 + jc * 16));
    const u32 st1 = swzf((u32)((c0 + 32) * 128 + jc * 16));

    float acc[8][4];
#pragma unroll
    for (int ng = 0; ng < 8; ng++)
#pragma unroll
        for (int r = 0; r < 4; r++) acc[ng][r] = 0.f;
    float accrs[4] = {0.f, 0.f, 0.f, 0.f};

    uint4 pvh0, pvh1;
    float4 psc = make_float4(0.f, 0.f, 0.f, 0.f);

    auto ldg_tile = [&](int t) {
        int j0 = t * 64;
        pvh0 = *(const uint4*)(hhp + (size_t)c0 * NT + j0 + jc * 8);
        pvh1 = *(const uint4*)(hhp + (size_t)(c0 + 32) * NT + j0 + jc * 8);
        if (tid < 64) psc = spkp[j0 + tid];
    };

    ldg_tile(0);

    const u32 su[2] = { smem_u32(sh_h[0]), smem_u32(sh_h[1]) };

    const int sub = l >> 3;
    const int brow = (l & 7) + ((sub >> 1) << 3);

    for (int t = 0; t < 16; t++) {
        int buf = t & 1;
        *(uint4*)((char*)sh_h[buf] + st0) = pvh0;
        *(uint4*)((char*)sh_h[buf] + st1) = pvh1;
        if (tid < 64) sh_sp[buf][tid] = psc;
        __syncthreads();
        if (t < 15) ldg_tile(t + 1);

        const float4* sp = sh_sp[buf];
        const ull m0 = mrow0[t];
        const ull m1 = mrow1[t];

#pragma unroll
        for (int q = 0; q < 4; q++) {
            const int jA = q * 16 + 2 * (l & 3);
            float4 p0 = sp[jA], p1 = sp[jA + 1], p2 = sp[jA + 8], p3 = sp[jA + 9];

            u32 ahi[4];
            {
                float eA = edgef(p0, dp0, (u32)(m0 >> jA) & 1u);
                float eB = edgef(p1, dp0, (u32)(m0 >> (jA + 1)) & 1u);
                float eC = edgef(p2, dp0, (u32)(m0 >> (jA + 8)) & 1u);
                float eD = edgef(p3, dp0, (u32)(m0 >> (jA + 9)) & 1u);
                ahi[0] = packh2(eA, eB);
                ahi[2] = packh2(eC, eD);
            }
            {
                float eA = edgef(p0, dp1, (u32)(m1 >> jA) & 1u);
                float eB = edgef(p1, dp1, (u32)(m1 >> (jA + 1)) & 1u);
                float eC = edgef(p2, dp1, (u32)(m1 >> (jA + 8)) & 1u);
                float eD = edgef(p3, dp1, (u32)(m1 >> (jA + 9)) & 1u);
                ahi[1] = packh2(eA, eB);
                ahi[3] = packh2(eC, eD);
            }

            mmaf16(accrs, ahi, ONESH, ONESH);

            u32 bh[16];
            const int bchunk = 2 * q + (sub & 1);
#pragma unroll
            for (int g = 0; g < 4; g++) {
                u32 off = swzf((u32)((g * 16 + brow) * 128 + bchunk * 16));
                ldsm4(bh + g * 4, su[buf] + off);
            }
#pragma unroll
            for (int g = 0; g < 4; g++) {
#pragma unroll
                for (int m = 0; m < 2; m++) {
                    int ng = g * 2 + m;
                    mmaf16(acc[ng], ahi, bh[g * 4 + 2 * m], bh[g * 4 + 2 * m + 1]);
                }
            }
        }
        __syncthreads();
    }

    float rinv0 = 1.0f / accrs[0];
    float rinv1 = 1.0f / accrs[2];

    const size_t ro0 = (size_t)(b * NT + i0 + r0) * fs + h * 64;
    const size_t ro1 = (size_t)(b * NT + i0 + r1) * fs + h * 64;
#pragma unroll
    for (int ng = 0; ng < 8; ng++) {
        int col = ng * 8 + 2 * (l & 3);
        float2 bb = *(const float2*)(bias + h * 64 + col);
        float2 o0, o1;
        o0.x = fmaxf(acc[ng][0] * rinv0 + bb.x, 0.f);
        o0.y = fmaxf(acc[ng][1] * rinv0 + bb.y, 0.f);
        o1.x = fmaxf(acc[ng][2] * rinv1 + bb.x, 0.f);
        o1.y = fmaxf(acc[ng][3] * rinv1 + bb.y, 0.f);
        if (wf32) {
            *(float2*)(xoutf + ro0 + col) = o0;
            *(float2*)(xoutf + ro1 + col) = o1;
        } else {
            u32 ph, pl;
            split2h(o0.x, o0.y, ph, pl);
            *(u32*)(xhi + ro0 + col) = ph;
            *(u32*)(xlo + ro0 + col) = pl;
            split2h(o1.x, o1.y, ph, pl);
            *(u32*)(xhi + ro1 + col) = ph;
            *(u32*)(xlo + ro1 + col) = pl;
        }
    }
}

// ---------------- readout --------------------------------------------------
__global__ void gsum_kernel(const float* __restrict__ x, float* __restrict__ g) {
    int b = blockIdx.x;
    int tid = threadIdx.x;
    int c = tid & 63, nq = tid >> 6;
    float acc = 0.f;
    for (int n = nq; n < NT; n += 4) acc += x[((size_t)b * NT + n) * 64 + c];
    __shared__ float sm[256];
    sm[tid] = acc;
    __syncthreads();
    if (tid < 64) g[b * 64 + tid] = sm[tid] + sm[64 + tid] + sm[128 + tid] + sm[192 + tid];
}

__global__ void z2_kernel(const float* __restrict__ g, const float* __restrict__ wg,
                          const float* __restrict__ bg, const float* __restrict__ wv,
                          float* __restrict__ z2) {
    int b = blockIdx.x;
    int c = threadIdx.x;
    float acc = bg[c];
    for (int k = 0; k < 64; k++) acc += g[b * 64 + k] * wg[c * 64 + k];
    float y = fmaxf(acc, 0.f) * wv[64 + c];
    __shared__ float sm[64];
    sm[c] = y;
    __syncthreads();
    if (c == 0) {
        float t = 0.f;
        for (int k = 0; k < 64; k++) t += sm[k];
        z2[b] = t;
    }
}

__global__ __launch_bounds__(256) void final_kernel(
    const float* __restrict__ x,
    const float* __restrict__ wn, const float* __restrict__ bn,
    const float* __restrict__ wv, const float* __restrict__ bv,
    const float* __restrict__ z2, float* __restrict__ out)
{
    __shared__ float wns[64][65];
    __shared__ float bns[64], wvs[64];
    int tid = threadIdx.x;
#pragma unroll
    for (int l = 0; l < 16; l++) {
        int f = tid + l * 256;
        wns[f >> 6][f & 63] = wn[f];
    }
    if (tid < 64) { bns[tid] = bn[tid]; wvs[tid] = wv[tid]; }
    __syncthreads();

    int row = blockIdx.x * 64 + (tid >> 2);
    int q = tid & 3;
    float xr[64];
#pragma unroll
    for (int k = 0; k < 64; k++) xr[k] = x[(size_t)row * 64 + k];
    float y = 0.f;
    for (int c16 = 0; c16 < 16; c16++) {
        int c = q * 16 + c16;
        float acc = bns[c];
#pragma unroll
        for (int k = 0; k < 64; k++) acc += xr[k] * wns[c][k];
        y += fmaxf(acc, 0.f) * wvs[c];
    }
    y += __shfl_xor_sync(0xffffffffu, y, 1);
    y += __shfl_xor_sync(0xffffffffu, y, 2);
    if (q == 0) out[row] = y + z2[row >> 10] + bv[0];
}

// ---------------- launch ----------------------------------------------------
extern "C" void kernel_launch(void* const* d_in, const int* in_sizes, int n_in,
                              void* d_out, int out_size)
{
    const float* xin = (const float*)d_in[0];
    const int*   adj = (const int*)d_in[1];
    const float* w1  = (const float*)d_in[2];
    const float* as1 = (const float*)d_in[3];
    const float* ad1 = (const float*)d_in[4];
    const float* b1  = (const float*)d_in[5];
    const float* w2  = (const float*)d_in[6];
    const float* as2 = (const float*)d_in[7];
    const float* ad2 = (const float*)d_in[8];
    const float* b2  = (const float*)d_in[9];
    const float* w3  = (const float*)d_in[10];
    const float* as3 = (const float*)d_in[11];
    const float* ad3 = (const float*)d_in[12];
    const float* b3  = (const float*)d_in[13];
    const float* wn  = (const float*)d_in[14];
    const float* bn  = (const float*)d_in[15];
    const float* wg  = (const float*)d_in[16];
    const float* bg  = (const float*)d_in[17];
    const float* wv  = (const float*)d_in[18];
    const float* bv  = (const float*)d_in[19];
    float* out = (float*)d_out;

    float *bufB, *gsm, *z2p;
    float4 *spk, *dpk;
    __half *hT, *xhi, *xlo, *w1h, *w2h, *w3h;
    u32* bits;
    cudaGetSymbolAddress((void**)&bufB, g_bufB);
    cudaGetSymbolAddress((void**)&spk,  g_spk);
    cudaGetSymbolAddress((void**)&dpk,  g_dpk);
    cudaGetSymbolAddress((void**)&hT,   g_hT);
    cudaGetSymbolAddress((void**)&xhi,  g_xhi);
    cudaGetSymbolAddress((void**)&xlo,  g_xlo);
    cudaGetSymbolAddress((void**)&w1h,  g_w1h);
    cudaGetSymbolAddress((void**)&w2h,  g_w2h);
    cudaGetSymbolAddress((void**)&w3h,  g_w3h);
    cudaGetSymbolAddress((void**)&bits, g_bits);
    cudaGetSymbolAddress((void**)&gsm,  g_gsum);
    cudaGetSymbolAddress((void**)&z2p,  g_z2);

    cudaFuncSetAttribute(gemm_h16, cudaFuncAttributeMaxDynamicSharedMemorySize, GH_SMEM);

    const int M = BATCH * NT;
    const ull* bits64 = (const ull*)bits;

    pack_adj_kernel<<<M / 8, 256>>>(adj, bits);
    convh_kernel<<<(256 * 64 / 4 + 255) / 256, 256>>>(w1, w1h, 256 * 64 / 4);
    convh_kernel<<<(256 * 256 / 4 + 255) / 256, 256>>>(w2, w2h, 256 * 256 / 4);
    convh_kernel<<<(64 * 256 / 4 + 255) / 256, 256>>>(w3, w3h, 64 * 256 / 4);
    xsplit_kernel<<<(M * 64 / 4 + 255) / 256, 256>>>(xin, xhi, xlo, M * 64 / 4);

    // layer 1: 64 -> 4x64 (pipelined fp16 gemm, K=64)
    gemm_h16<<<dim3(M / 128, 4), 256, GH_SMEM>>>(xhi, xlo, w1h, as1, ad1,
                                                 spk, dpk, hT, 64);
    agg_mma_kernel<<<dim3(NT / 128, 4, BATCH), 256>>>(
        hT, spk, dpk, bits64, b1, xhi, xlo, nullptr, 0, 4);

    // layer 2: 4x64 -> 4x64
    gemm_h16<<<dim3(M / 128, 4), 256, GH_SMEM>>>(xhi, xlo, w2h, as2, ad2,
                                                 spk, dpk, hT, 256);
    agg_mma_kernel<<<dim3(NT / 128, 4, BATCH), 256>>>(
        hT, spk, dpk, bits64, b2, xhi, xlo, nullptr, 0, 4);

    // layer 3: 4x64 -> 64 (H=1)
    gemm_h16<<<dim3(M / 128, 1), 256, GH_SMEM>>>(xhi, xlo, w3h, as3, ad3,
                                                 spk, dpk, hT, 256);
    agg_mma_kernel<<<dim3(NT / 128, 1, BATCH), 256>>>(
        hT, spk, dpk, bits64, b3, nullptr, nullptr, bufB, 1, 1);

    // readout
    gsum_kernel<<<BATCH, 256>>>(bufB, gsm);
    z2_kernel<<<BATCH, 64>>>(gsm, wg, bg, wv, z2p);
    final_kernel<<<M / 64, 256>>>(bufB, wn, bn, wv, bv, z2p, out);
}

// round 16
// speedup vs baseline: 1.0518x; 1.0518x over previous
#include <cuda_runtime.h>
#include <cuda_fp16.h>
#include <cstdint>

#define BATCH 8
#define NT    1024
typedef unsigned long long ull;
typedef unsigned int u32;

// ---------------- scratch (__device__ globals; no allocation allowed) ------
__device__ __align__(16) float g_bufB[BATCH * NT * 64];      // layer3 f32 out
// features pre-split to fp16 hi/lo planes [b][node][fs]
__device__ __align__(16) __half g_xhi[BATCH * NT * 256];
__device__ __align__(16) __half g_xlo[BATCH * NT * 256];
// fp16 weights (single plane)
__device__ __align__(16) __half g_w1h[256 * 64];
__device__ __align__(16) __half g_w2h[256 * 256];
__device__ __align__(16) __half g_w3h[64 * 256];
// packed source scores (s, Es, Es2, 0) and dest scores (d, Ed, Ed2, 0), [h][b][node]
__device__ __align__(16) float4 g_spk[4 * BATCH * NT];
__device__ __align__(16) float4 g_dpk[4 * BATCH * NT];
// pre-transposed fp16 features [h][b][c=64][node=1024]
__device__ __align__(16) __half g_hT[4 * BATCH * 64 * NT];
__device__ __align__(16) u32   g_bits[BATCH * NT * (NT / 32)];
__device__ __align__(16) float g_gsum[BATCH * 64];
__device__ __align__(16) float g_z2[BATCH];

// ---------------- helpers --------------------------------------------------
__device__ __forceinline__ uint32_t smem_u32(const void* p) {
    uint32_t a;
    asm("{ .reg .u64 t; cvta.to.shared.u64 t, %1; cvt.u32.u64 %0, t; }" : "=r"(a) : "l"(p));
    return a;
}

__device__ __forceinline__ void ldsm4(u32* r, u32 addr) {
    asm volatile("ldmatrix.sync.aligned.m8n8.x4.shared.b16 {%0,%1,%2,%3}, [%4];"
                 : "=r"(r[0]), "=r"(r[1]), "=r"(r[2]), "=r"(r[3]) : "r"(addr));
}

__device__ __forceinline__ void mmaf16(float* c, const u32* a, u32 b0, u32 b1) {
    asm volatile(
        "mma.sync.aligned.m16n8k16.row.col.f32.f16.f16.f32 "
        "{%0,%1,%2,%3}, {%4,%5,%6,%7}, {%8,%9}, {%0,%1,%2,%3};"
        : "+f"(c[0]), "+f"(c[1]), "+f"(c[2]), "+f"(c[3])
        : "r"(a[0]), "r"(a[1]), "r"(a[2]), "r"(a[3]), "r"(b0), "r"(b1));
}

// e_ij = adjbit * ( s_j + d_i > 0 ? Es_j*Ed_i : Es2_j*Ed2_i )
__device__ __forceinline__ float edgef(float4 p, float4 dp, u32 bit) {
    float e = (p.x + dp.x > 0.f) ? p.y * dp.y : p.z * dp.z;
    return bit ? e : 0.f;
}

// pack two fp32 into f16x2 (lower = ex, upper = ey) in one cvt
__device__ __forceinline__ u32 packh2(float ex, float ey) {
    u32 r;
    asm("cvt.rn.f16x2.f32 %0, %1, %2;" : "=r"(r) : "f"(ey), "f"(ex));
    return r;
}

// fp16 hi/lo split of a pair, packed
__device__ __forceinline__ void split2h(float x0, float x1, u32& hi, u32& lo) {
    hi = packh2(x0, x1);
    __half2 hv = *(__half2*)&hi;
    float2 bk = __half22float2(hv);
    lo = packh2(x0 - bk.x, x1 - bk.y);
}

__device__ __forceinline__ u32 swzf(u32 off) { return off ^ ((off >> 3) & 0x70); }

__device__ __forceinline__ void cpasync16(u32 dst, const void* src) {
    asm volatile("cp.async.cg.shared.global [%0], [%1], 16;" :: "r"(dst), "l"(src) : "memory");
}
#define CP_COMMIT() asm volatile("cp.async.commit_group;" ::: "memory")
#define CP_WAIT0()  asm volatile("cp.async.wait_group 0;" ::: "memory")

#define ONESH 0x3C003C00u   // two fp16 1.0

// ---------------- adj bit packing (with self loops) ------------------------
// 256 threads = 8 warps; warp handles one row. grid = M/8.
__global__ __launch_bounds__(256) void pack_adj_kernel(
    const int* __restrict__ adj, u32* __restrict__ bits)
{
    int row = blockIdx.x * 8 + (threadIdx.x >> 5);
    int lane = threadIdx.x & 31;
    int i = row & (NT - 1);
    const int* arow = adj + (size_t)row * NT;
#pragma unroll 8
    for (int w = 0; w < 32; w++) {
        int j = w * 32 + lane;
        unsigned m = __ballot_sync(0xffffffffu, (arow[j] > 0) || (j == i));
        if (lane == 0) bits[row * 32 + w] = m;
    }
}

// ---------------- fused prep: x split + all weight conversions -------------
// block ranges: [0,512) xsplit, [512,528) w1, [528,592) w2, [592,608) w3
__global__ __launch_bounds__(256) void prep_kernel(
    const float* __restrict__ xin,
    const float* __restrict__ w1, const float* __restrict__ w2,
    const float* __restrict__ w3,
    __half* __restrict__ xhi, __half* __restrict__ xlo,
    __half* __restrict__ w1h, __half* __restrict__ w2h, __half* __restrict__ w3h)
{
    int bk = blockIdx.x;
    if (bk < 512) {
        int i = bk * 256 + threadIdx.x;     // quad index, 131072 total
        float4 v = *(const float4*)(xin + (size_t)i * 4);
        u32 h0, h1, l0, l1;
        split2h(v.x, v.y, h0, l0);
        split2h(v.z, v.w, h1, l1);
        *(uint2*)(xhi + (size_t)i * 4) = make_uint2(h0, h1);
        *(uint2*)(xlo + (size_t)i * 4) = make_uint2(l0, l1);
        return;
    }
    const float* src;
    __half* dst;
    int i;
    if (bk < 528)      { src = w1; dst = w1h; i = (bk - 512) * 256 + threadIdx.x; }
    else if (bk < 592) { src = w2; dst = w2h; i = (bk - 528) * 256 + threadIdx.x; }
    else               { src = w3; dst = w3h; i = (bk - 592) * 256 + threadIdx.x; }
    float4 v = *(const float4*)(src + (size_t)i * 4);
    uint2 o;
    o.x = packh2(v.x, v.y);
    o.y = packh2(v.z, v.w);
    *(uint2*)(dst + (size_t)i * 4) = o;
}

// ---------------- GEMM: all-fp16 operands, cp.async pipeline ---------------
// X pre-split hi/lo planes [b][node][K], W pre-converted fp16. 2 MMA passes.
// Epilogue: attention scores + fp16 transposed feature write.
#define TPAD 136
#define GH_BUF   40960                      // Xh 16K + Xl 16K + W 8K
#define GH_SMEM  (2 * GH_BUF)
__global__ __launch_bounds__(256) void gemm_h16(
    const __half* __restrict__ Xh, const __half* __restrict__ Xl,
    const __half* __restrict__ Wh,
    const float* __restrict__ a_src, const float* __restrict__ a_dst,
    float4* __restrict__ spk, float4* __restrict__ dpk,
    __half* __restrict__ hT, int K)
{
    extern __shared__ __align__(128) char smem[];
    const u32 sb = smem_u32(smem);

    const int tid = threadIdx.x;
    const int w = tid >> 5, l = tid & 31;
    const int h = blockIdx.y;
    const int m0 = blockIdx.x * 128, n0 = h * 64;

    float acc[8][4];
#pragma unroll
    for (int ng = 0; ng < 8; ng++)
#pragma unroll
        for (int r = 0; r < 4; r++) acc[ng][r] = 0.f;

    const int arow = w * 16 + (l & 7) + ((l >> 3) & 1) * 8;
    const int akh  = (l >> 4);
    const int sub = l >> 3;
    const int brow = (l & 7) + ((sub >> 1) << 3);

    const int nIter = K / 64;

    auto issue = [&](int t) {
        int k0 = t * 64;
        u32 base = sb + (t & 1) * GH_BUF;
#pragma unroll
        for (int i = 0; i < 4; i++) {
            int c = tid + i * 256;
            int row = c >> 3, kg = c & 7;
            u32 off = swzf((u32)(row * 128 + kg * 16));
            cpasync16(base + off,         Xh + (size_t)(m0 + row) * K + k0 + kg * 8);
            cpasync16(base + 16384 + off, Xl + (size_t)(m0 + row) * K + k0 + kg * 8);
        }
#pragma unroll
        for (int i = 0; i < 2; i++) {
            int c = tid + i * 256;
            int row = c >> 3, kg = c & 7;
            u32 off = swzf((u32)(row * 128 + kg * 16));
            cpasync16(base + 32768 + off, Wh + (size_t)(n0 + row) * K + k0 + kg * 8);
        }
        CP_COMMIT();
    };

    issue(0);

    for (int t = 0; t < nIter; t++) {
        CP_WAIT0();
        __syncthreads();
        if (t + 1 < nIter) issue(t + 1);

        u32 base = sb + (t & 1) * GH_BUF;
#pragma unroll
        for (int q = 0; q < 4; q++) {
            u32 ah[4], al[4];
            u32 aoff = swzf((u32)(arow * 128 + q * 32 + akh * 16));
            ldsm4(ah, base + aoff);
            ldsm4(al, base + 16384 + aoff);
            const int bchunk = 2 * q + (sub & 1);
            u32 bh[16];
#pragma unroll
            for (int g = 0; g < 4; g++) {
                u32 off = swzf((u32)((g * 16 + brow) * 128 + bchunk * 16));
                ldsm4(bh + g * 4, base + 32768 + off);
            }
#pragma unroll
            for (int g = 0; g < 4; g++) {
#pragma unroll
                for (int m = 0; m < 2; m++) {
                    int ng = g * 2 + m;
                    u32 b0 = bh[g * 4 + 2 * m], b1 = bh[g * 4 + 2 * m + 1];
                    mmaf16(acc[ng], ah, b0, b1);
                    mmaf16(acc[ng], al, b0, b1);
                }
            }
        }
        __syncthreads();
    }

    const int r0 = w * 16 + (l >> 2);
    const int r1 = r0 + 8;

    // ---- epilogue 1: attention scores ----
    {
        float s0 = 0.f, d0 = 0.f, s1 = 0.f, d1 = 0.f;
#pragma unroll
        for (int ng = 0; ng < 8; ng++) {
            int col = ng * 8 + 2 * (l & 3);
            float2 av = *(const float2*)(a_src + n0 + col);
            float2 dv = *(const float2*)(a_dst + n0 + col);
            s0 += acc[ng][0] * av.x + acc[ng][1] * av.y;
            d0 += acc[ng][0] * dv.x + acc[ng][1] * dv.y;
            s1 += acc[ng][2] * av.x + acc[ng][3] * av.y;
            d1 += acc[ng][2] * dv.x + acc[ng][3] * dv.y;
        }
        s0 += __shfl_xor_sync(0xffffffffu, s0, 1);
        s0 += __shfl_xor_sync(0xffffffffu, s0, 2);
        d0 += __shfl_xor_sync(0xffffffffu, d0, 1);
        d0 += __shfl_xor_sync(0xffffffffu, d0, 2);
        s1 += __shfl_xor_sync(0xffffffffu, s1, 1);
        s1 += __shfl_xor_sync(0xffffffffu, s1, 2);
        d1 += __shfl_xor_sync(0xffffffffu, d1, 1);
        d1 += __shfl_xor_sync(0xffffffffu, d1, 2);
        if ((l & 3) == 0) {
            int idx0 = h * (BATCH * NT) + m0 + r0;
            int idx1 = h * (BATCH * NT) + m0 + r1;
            spk[idx0] = make_float4(s0, __expf(s0), __expf(0.2f * s0), 0.f);
            dpk[idx0] = make_float4(d0, __expf(d0), __expf(0.2f * d0), 0.f);
            spk[idx1] = make_float4(s1, __expf(s1), __expf(0.2f * s1), 0.f);
            dpk[idx1] = make_float4(d1, __expf(d1), __expf(0.2f * d1), 0.f);
        }
    }

    // ---- epilogue 2: fp16 transpose via smem bounce ----
    __syncthreads();
    unsigned short* Th = (unsigned short*)smem;
#pragma unroll
    for (int ng = 0; ng < 8; ng++) {
        int col = ng * 8 + 2 * (l & 3);
#pragma unroll
        for (int v = 0; v < 4; v++) {
            int cc = col + (v & 1);
            int node = (v < 2) ? r0 : r1;
            u32 p = packh2(acc[ng][v], 0.f);
            Th[cc * TPAD + node] = (unsigned short)(p & 0xffffu);
        }
    }
    __syncthreads();

    const int b = m0 >> 10;
    const int node0 = m0 & (NT - 1);
    const size_t gbase = ((size_t)((h * BATCH + b) * 64)) * NT + node0;
    {
        int c = tid >> 2;
#pragma unroll
        for (int i = 0; i < 4; i++) {
            int nch = (tid & 3) + 4 * i;
            uint4 vh = *(const uint4*)(Th + c * TPAD + nch * 8);
            *(uint4*)(hT + gbase + (size_t)c * NT + nch * 8) = vh;
        }
    }
}

// ---------------- HMMA aggregation (fp16 single-pass) ----------------------
// Epilogue writes either f32 (layer 3, for readout) or pre-split fp16 hi/lo
// planes (layers 1-2, consumed by gemm_h16's cp.async staging).
__global__ __launch_bounds__(256, 2) void agg_mma_kernel(
    const __half* __restrict__ hTA,
    const float4* __restrict__ spkA, const float4* __restrict__ dpkA,
    const ull* __restrict__ bits64,
    const float* __restrict__ bias,
    __half* __restrict__ xhi, __half* __restrict__ xlo,
    float* __restrict__ xoutf, int wf32, int H)
{
    __shared__ __align__(16) __half sh_h[2][64 * 64];
    __shared__ __align__(16) float4 sh_sp[2][64];

    const int tid = threadIdx.x;
    const int w = tid >> 5, l = tid & 31;
    const int b = blockIdx.z, h = blockIdx.y;
    const int i0 = blockIdx.x * 128;
    const int hb = h * BATCH + b;
    const int fs = H * 64;

    const int r0 = w * 16 + (l >> 2);
    const int r1 = r0 + 8;
    const float4 dp0 = dpkA[hb * NT + i0 + r0];
    const float4 dp1 = dpkA[hb * NT + i0 + r1];
    const ull* mrow0 = bits64 + (size_t)(b * NT + i0 + r0) * 16;
    const ull* mrow1 = bits64 + (size_t)(b * NT + i0 + r1) * 16;

    const float4* spkp = spkA + hb * NT;
    const __half* hhp = hTA + (size_t)hb * 64 * NT;

    const int c0 = tid >> 3, jc = tid & 7;
    const u32 st0 = swzf((u32)(c0 * 128 + jc * 16));
    const u32 st1 = swzf((u32)((c0 + 32) * 128 + jc * 16));

    float acc[8][4];
#pragma unroll
    for (int ng = 0; ng < 8; ng++)
#pragma unroll
        for (int r = 0; r < 4; r++) acc[ng][r] = 0.f;
    float accrs[4] = {0.f, 0.f, 0.f, 0.f};

    uint4 pvh0, pvh1;
    float4 psc = make_float4(0.f, 0.f, 0.f, 0.f);

    auto ldg_tile = [&](int t) {
        int j0 = t * 64;
        pvh0 = *(const uint4*)(hhp + (size_t)c0 * NT + j0 + jc * 8);
        pvh1 = *(const uint4*)(hhp + (size_t)(c0 + 32) * NT + j0 + jc * 8);
        if (tid < 64) psc = spkp[j0 + tid];
    };

    ldg_tile(0);

    const u32 su[2] = { smem_u32(sh_h[0]), smem_u32(sh_h[1]) };

    const int sub = l >> 3;
    const int brow = (l & 7) + ((sub >> 1) << 3);

    for (int t = 0; t < 16; t++) {
        int buf = t & 1;
        *(uint4*)((char*)sh_h[buf] + st0) = pvh0;
        *(uint4*)((char*)sh_h[buf] + st1) = pvh1;
        if (tid < 64) sh_sp[buf][tid] = psc;
        __syncthreads();
        if (t < 15) ldg_tile(t + 1);

        const float4* sp = sh_sp[buf];
        const ull m0 = mrow0[t];
        const ull m1 = mrow1[t];

#pragma unroll
        for (int q = 0; q < 4; q++) {
            const int jA = q * 16 + 2 * (l & 3);
            float4 p0 = sp[jA], p1 = sp[jA + 1], p2 = sp[jA + 8], p3 = sp[jA + 9];

            u32 ahi[4];
            {
                float eA = edgef(p0, dp0, (u32)(m0 >> jA) & 1u);
                float eB = edgef(p1, dp0, (u32)(m0 >> (jA + 1)) & 1u);
                float eC = edgef(p2, dp0, (u32)(m0 >> (jA + 8)) & 1u);
                float eD = edgef(p3, dp0, (u32)(m0 >> (jA + 9)) & 1u);
                ahi[0] = packh2(eA, eB);
                ahi[2] = packh2(eC, eD);
            }
            {
                float eA = edgef(p0, dp1, (u32)(m1 >> jA) & 1u);
                float eB = edgef(p1, dp1, (u32)(m1 >> (jA + 1)) & 1u);
                float eC = edgef(p2, dp1, (u32)(m1 >> (jA + 8)) & 1u);
                float eD = edgef(p3, dp1, (u32)(m1 >> (jA + 9)) & 1u);
                ahi[1] = packh2(eA, eB);
                ahi[3] = packh2(eC, eD);
            }

            mmaf16(accrs, ahi, ONESH, ONESH);

            u32 bh[16];
            const int bchunk = 2 * q + (sub & 1);
#pragma unroll
            for (int g = 0; g < 4; g++) {
                u32 off = swzf((u32)((g * 16 + brow) * 128 + bchunk * 16));
                ldsm4(bh + g * 4, su[buf] + off);
            }
#pragma unroll
            for (int g = 0; g < 4; g++) {
#pragma unroll
                for (int m = 0; m < 2; m++) {
                    int ng = g * 2 + m;
                    mmaf16(acc[ng], ahi, bh[g * 4 + 2 * m], bh[g * 4 + 2 * m + 1]);
                }
            }
        }
        __syncthreads();
    }

    float rinv0 = 1.0f / accrs[0];
    float rinv1 = 1.0f / accrs[2];

    const size_t ro0 = (size_t)(b * NT + i0 + r0) * fs + h * 64;
    const size_t ro1 = (size_t)(b * NT + i0 + r1) * fs + h * 64;
#pragma unroll
    for (int ng = 0; ng < 8; ng++) {
        int col = ng * 8 + 2 * (l & 3);
        float2 bb = *(const float2*)(bias + h * 64 + col);
        float2 o0, o1;
        o0.x = fmaxf(acc[ng][0] * rinv0 + bb.x, 0.f);
        o0.y = fmaxf(acc[ng][1] * rinv0 + bb.y, 0.f);
        o1.x = fmaxf(acc[ng][2] * rinv1 + bb.x, 0.f);
        o1.y = fmaxf(acc[ng][3] * rinv1 + bb.y, 0.f);
        if (wf32) {
            *(float2*)(xoutf + ro0 + col) = o0;
            *(float2*)(xoutf + ro1 + col) = o1;
        } else {
            u32 ph, pl;
            split2h(o0.x, o0.y, ph, pl);
            *(u32*)(xhi + ro0 + col) = ph;
            *(u32*)(xlo + ro0 + col) = pl;
            split2h(o1.x, o1.y, ph, pl);
            *(u32*)(xhi + ro1 + col) = ph;
            *(u32*)(xlo + ro1 + col) = pl;
        }
    }
}

// ---------------- readout --------------------------------------------------
__global__ void gsum_kernel(const float* __restrict__ x, float* __restrict__ g) {
    int b = blockIdx.x;
    int tid = threadIdx.x;
    int c = tid & 63, nq = tid >> 6;
    float acc = 0.f;
    for (int n = nq; n < NT; n += 4) acc += x[((size_t)b * NT + n) * 64 + c];
    __shared__ float sm[256];
    sm[tid] = acc;
    __syncthreads();
    if (tid < 64) g[b * 64 + tid] = sm[tid] + sm[64 + tid] + sm[128 + tid] + sm[192 + tid];
}

__global__ void z2_kernel(const float* __restrict__ g, const float* __restrict__ wg,
                          const float* __restrict__ bg, const float* __restrict__ wv,
                          float* __restrict__ z2) {
    int b = blockIdx.x;
    int c = threadIdx.x;
    float acc = bg[c];
    for (int k = 0; k < 64; k++) acc += g[b * 64 + k] * wg[c * 64 + k];
    float y = fmaxf(acc, 0.f) * wv[64 + c];
    __shared__ float sm[64];
    sm[c] = y;
    __syncthreads();
    if (c == 0) {
        float t = 0.f;
        for (int k = 0; k < 64; k++) t += sm[k];
        z2[b] = t;
    }
}

__global__ __launch_bounds__(256) void final_kernel(
    const float* __restrict__ x,
    const float* __restrict__ wn, const float* __restrict__ bn,
    const float* __restrict__ wv, const float* __restrict__ bv,
    const float* __restrict__ z2, float* __restrict__ out)
{
    __shared__ float wns[64][65];
    __shared__ float bns[64], wvs[64];
    int tid = threadIdx.x;
#pragma unroll
    for (int l = 0; l < 16; l++) {
        int f = tid + l * 256;
        wns[f >> 6][f & 63] = wn[f];
    }
    if (tid < 64) { bns[tid] = bn[tid]; wvs[tid] = wv[tid]; }
    __syncthreads();

    int row = blockIdx.x * 64 + (tid >> 2);
    int q = tid & 3;
    float xr[64];
#pragma unroll
    for (int k = 0; k < 64; k++) xr[k] = x[(size_t)row * 64 + k];
    float y = 0.f;
    for (int c16 = 0; c16 < 16; c16++) {
        int c = q * 16 + c16;
        float acc = bns[c];
#pragma unroll
        for (int k = 0; k < 64; k++) acc += xr[k] * wns[c][k];
        y += fmaxf(acc, 0.f) * wvs[c];
    }
    y += __shfl_xor_sync(0xffffffffu, y, 1);
    y += __shfl_xor_sync(0xffffffffu, y, 2);
    if (q == 0) out[row] = y + z2[row >> 10] + bv[0];
}

// ---------------- launch ----------------------------------------------------
extern "C" void kernel_launch(void* const* d_in, const int* in_sizes, int n_in,
                              void* d_out, int out_size)
{
    const float* xin = (const float*)d_in[0];
    const int*   adj = (const int*)d_in[1];
    const float* w1  = (const float*)d_in[2];
    const float* as1 = (const float*)d_in[3];
    const float* ad1 = (const float*)d_in[4];
    const float* b1  = (const float*)d_in[5];
    const float* w2  = (const float*)d_in[6];
    const float* as2 = (const float*)d_in[7];
    const float* ad2 = (const float*)d_in[8];
    const float* b2  = (const float*)d_in[9];
    const float* w3  = (const float*)d_in[10];
    const float* as3 = (const float*)d_in[11];
    const float* ad3 = (const float*)d_in[12];
    const float* b3  = (const float*)d_in[13];
    const float* wn  = (const float*)d_in[14];
    const float* bn  = (const float*)d_in[15];
    const float* wg  = (const float*)d_in[16];
    const float* bg  = (const float*)d_in[17];
    const float* wv  = (const float*)d_in[18];
    const float* bv  = (const float*)d_in[19];
    float* out = (float*)d_out;

    float *bufB, *gsm, *z2p;
    float4 *spk, *dpk;
    __half *hT, *xhi, *xlo, *w1h, *w2h, *w3h;
    u32* bits;
    cudaGetSymbolAddress((void**)&bufB, g_bufB);
    cudaGetSymbolAddress((void**)&spk,  g_spk);
    cudaGetSymbolAddress((void**)&dpk,  g_dpk);
    cudaGetSymbolAddress((void**)&hT,   g_hT);
    cudaGetSymbolAddress((void**)&xhi,  g_xhi);
    cudaGetSymbolAddress((void**)&xlo,  g_xlo);
    cudaGetSymbolAddress((void**)&w1h,  g_w1h);
    cudaGetSymbolAddress((void**)&w2h,  g_w2h);
    cudaGetSymbolAddress((void**)&w3h,  g_w3h);
    cudaGetSymbolAddress((void**)&bits, g_bits);
    cudaGetSymbolAddress((void**)&gsm,  g_gsum);
    cudaGetSymbolAddress((void**)&z2p,  g_z2);

    cudaFuncSetAttribute(gemm_h16, cudaFuncAttributeMaxDynamicSharedMemorySize, GH_SMEM);

    const int M = BATCH * NT;
    const ull* bits64 = (const ull*)bits;

    pack_adj_kernel<<<M / 8, 256>>>(adj, bits);
    prep_kernel<<<608, 256>>>(xin, w1, w2, w3, xhi, xlo, w1h, w2h, w3h);

    // layer 1: 64 -> 4x64 (pipelined fp16 gemm, K=64)
    gemm_h16<<<dim3(M / 128, 4), 256, GH_SMEM>>>(xhi, xlo, w1h, as1, ad1,
                                                 spk, dpk, hT, 64);
    agg_mma_kernel<<<dim3(NT / 128, 4, BATCH), 256>>>(
        hT, spk, dpk, bits64, b1, xhi, xlo, nullptr, 0, 4);

    // layer 2: 4x64 -> 4x64
    gemm_h16<<<dim3(M / 128, 4), 256, GH_SMEM>>>(xhi, xlo, w2h, as2, ad2,
                                                 spk, dpk, hT, 256);
    agg_mma_kernel<<<dim3(NT / 128, 4, BATCH), 256>>>(
        hT, spk, dpk, bits64, b2, xhi, xlo, nullptr, 0, 4);

    // layer 3: 4x64 -> 64 (H=1)
    gemm_h16<<<dim3(M / 128, 1), 256, GH_SMEM>>>(xhi, xlo, w3h, as3, ad3,
                                                 spk, dpk, hT, 256);
    agg_mma_kernel<<<dim3(NT / 128, 1, BATCH), 256>>>(
        hT, spk, dpk, bits64, b3, nullptr, nullptr, bufB, 1, 1);

    // readout
    gsum_kernel<<<BATCH, 256>>>(bufB, gsm);
    z2_kernel<<<BATCH, 64>>>(gsm, wg, bg, wv, z2p);
    final_kernel<<<M / 64, 256>>>(bufB, wn, bn, wv, bv, z2p, out);
}

// round 17
// speedup vs baseline: 1.1190x; 1.0638x over previous
#include <cuda_runtime.h>
#include <cuda_fp16.h>
#include <cstdint>

#define BATCH 8
#define NT    1024
typedef unsigned long long ull;
typedef unsigned int u32;

// ---------------- scratch (__device__ globals; no allocation allowed) ------
__device__ __align__(16) float g_bufB[BATCH * NT * 64];      // layer3 f32 out
// features pre-split to fp16 hi/lo planes [b][node][fs]
__device__ __align__(16) __half g_xhi[BATCH * NT * 256];
__device__ __align__(16) __half g_xlo[BATCH * NT * 256];
// fp16 weights (single plane)
__device__ __align__(16) __half g_w1h[256 * 64];
__device__ __align__(16) __half g_w2h[256 * 256];
__device__ __align__(16) __half g_w3h[64 * 256];
// fp16 source-score SoA planes [h][b][node]
__device__ __align__(16) __half g_s16[4 * BATCH * NT];
__device__ __align__(16) __half g_e16[4 * BATCH * NT];
__device__ __align__(16) __half g_f16[4 * BATCH * NT];
// dest scores (d, Ed, Ed2, 0) fp32 [h][b][node]
__device__ __align__(16) float4 g_dpk[4 * BATCH * NT];
// pre-transposed fp16 features [h][b][c=64][node=1024]
__device__ __align__(16) __half g_hT[4 * BATCH * 64 * NT];
__device__ __align__(16) u32   g_bits[BATCH * NT * (NT / 32)];
__device__ __align__(16) float g_z2[BATCH];

// ---------------- helpers --------------------------------------------------
__device__ __forceinline__ uint32_t smem_u32(const void* p) {
    uint32_t a;
    asm("{ .reg .u64 t; cvta.to.shared.u64 t, %1; cvt.u32.u64 %0, t; }" : "=r"(a) : "l"(p));
    return a;
}

__device__ __forceinline__ void ldsm4(u32* r, u32 addr) {
    asm volatile("ldmatrix.sync.aligned.m8n8.x4.shared.b16 {%0,%1,%2,%3}, [%4];"
                 : "=r"(r[0]), "=r"(r[1]), "=r"(r[2]), "=r"(r[3]) : "r"(addr));
}

__device__ __forceinline__ void mmaf16(float* c, const u32* a, u32 b0, u32 b1) {
    asm volatile(
        "mma.sync.aligned.m16n8k16.row.col.f32.f16.f16.f32 "
        "{%0,%1,%2,%3}, {%4,%5,%6,%7}, {%8,%9}, {%0,%1,%2,%3};"
        : "+f"(c[0]), "+f"(c[1]), "+f"(c[2]), "+f"(c[3])
        : "r"(a[0]), "r"(a[1]), "r"(a[2]), "r"(a[3]), "r"(b0), "r"(b1));
}

// pack two fp32 into f16x2 (lower = ex, upper = ey) in one cvt
__device__ __forceinline__ u32 packh2(float ex, float ey) {
    u32 r;
    asm("cvt.rn.f16x2.f32 %0, %1, %2;" : "=r"(r) : "f"(ey), "f"(ex));
    return r;
}

// fp16 hi/lo split of a pair, packed
__device__ __forceinline__ void split2h(float x0, float x1, u32& hi, u32& lo) {
    hi = packh2(x0, x1);
    __half2 hv = *(__half2*)&hi;
    float2 bk = __half22float2(hv);
    lo = packh2(x0 - bk.x, x1 - bk.y);
}

// f16x2 arithmetic (raw u32 carriers)
__device__ __forceinline__ u32 h2add(u32 a, u32 b) {
    u32 r; asm("add.f16x2 %0, %1, %2;" : "=r"(r) : "r"(a), "r"(b)); return r;
}
__device__ __forceinline__ u32 h2mul(u32 a, u32 b) {
    u32 r; asm("mul.f16x2 %0, %1, %2;" : "=r"(r) : "r"(a), "r"(b)); return r;
}
// per-half 0xFFFF mask where a > b
__device__ __forceinline__ u32 h2gtmask(u32 a, u32 b) {
    u32 r; asm("set.gt.u32.f16x2 %0, %1, %2;" : "=r"(r) : "r"(a), "r"(b)); return r;
}
__device__ __forceinline__ u32 mask2(u32 b2) {
    return ((b2 & 1u) ? 0x0000FFFFu : 0u) | ((b2 & 2u) ? 0xFFFF0000u : 0u);
}

__device__ __forceinline__ u32 swzf(u32 off) { return off ^ ((off >> 3) & 0x70); }

__device__ __forceinline__ void cpasync16(u32 dst, const void* src) {
    asm volatile("cp.async.cg.shared.global [%0], [%1], 16;" :: "r"(dst), "l"(src) : "memory");
}
#define CP_COMMIT() asm volatile("cp.async.commit_group;" ::: "memory")
#define CP_WAIT0()  asm volatile("cp.async.wait_group 0;" ::: "memory")

#define ONESH 0x3C003C00u   // two fp16 1.0

// ---------------- fused prologue: adj pack + x split + weight convert ------
// blocks [0,1024): pack_adj (8 rows each); [1024,1536): xsplit;
// [1536,1552): w1; [1552,1616): w2; [1616,1632): w3
__global__ __launch_bounds__(256) void prep_all_kernel(
    const int* __restrict__ adj, u32* __restrict__ bits,
    const float* __restrict__ xin,
    const float* __restrict__ w1, const float* __restrict__ w2,
    const float* __restrict__ w3,
    __half* __restrict__ xhi, __half* __restrict__ xlo,
    __half* __restrict__ w1h, __half* __restrict__ w2h, __half* __restrict__ w3h)
{
    int bk = blockIdx.x;
    if (bk < 1024) {
        int row = bk * 8 + (threadIdx.x >> 5);
        int lane = threadIdx.x & 31;
        int i = row & (NT - 1);
        const int* arow = adj + (size_t)row * NT;
#pragma unroll 8
        for (int w = 0; w < 32; w++) {
            int j = w * 32 + lane;
            unsigned m = __ballot_sync(0xffffffffu, (arow[j] > 0) || (j == i));
            if (lane == 0) bits[row * 32 + w] = m;
        }
        return;
    }
    if (bk < 1536) {
        int i = (bk - 1024) * 256 + threadIdx.x;
        float4 v = *(const float4*)(xin + (size_t)i * 4);
        u32 h0, h1, l0, l1;
        split2h(v.x, v.y, h0, l0);
        split2h(v.z, v.w, h1, l1);
        *(uint2*)(xhi + (size_t)i * 4) = make_uint2(h0, h1);
        *(uint2*)(xlo + (size_t)i * 4) = make_uint2(l0, l1);
        return;
    }
    const float* src;
    __half* dst;
    int i;
    if (bk < 1552)      { src = w1; dst = w1h; i = (bk - 1536) * 256 + threadIdx.x; }
    else if (bk < 1616) { src = w2; dst = w2h; i = (bk - 1552) * 256 + threadIdx.x; }
    else                { src = w3; dst = w3h; i = (bk - 1616) * 256 + threadIdx.x; }
    float4 v = *(const float4*)(src + (size_t)i * 4);
    uint2 o;
    o.x = packh2(v.x, v.y);
    o.y = packh2(v.z, v.w);
    *(uint2*)(dst + (size_t)i * 4) = o;
}

// ---------------- GEMM: all-fp16 operands, cp.async pipeline ---------------
#define TPAD 136
#define GH_BUF   40960
#define GH_SMEM  (2 * GH_BUF)
__global__ __launch_bounds__(256) void gemm_h16(
    const __half* __restrict__ Xh, const __half* __restrict__ Xl,
    const __half* __restrict__ Wh,
    const float* __restrict__ a_src, const float* __restrict__ a_dst,
    __half* __restrict__ s16, __half* __restrict__ e16, __half* __restrict__ f16,
    float4* __restrict__ dpk,
    __half* __restrict__ hT, int K)
{
    extern __shared__ __align__(128) char smem[];
    const u32 sb = smem_u32(smem);

    const int tid = threadIdx.x;
    const int w = tid >> 5, l = tid & 31;
    const int h = blockIdx.y;
    const int m0 = blockIdx.x * 128, n0 = h * 64;

    float acc[8][4];
#pragma unroll
    for (int ng = 0; ng < 8; ng++)
#pragma unroll
        for (int r = 0; r < 4; r++) acc[ng][r] = 0.f;

    const int arow = w * 16 + (l & 7) + ((l >> 3) & 1) * 8;
    const int akh  = (l >> 4);
    const int sub = l >> 3;
    const int brow = (l & 7) + ((sub >> 1) << 3);

    const int nIter = K / 64;

    auto issue = [&](int t) {
        int k0 = t * 64;
        u32 base = sb + (t & 1) * GH_BUF;
#pragma unroll
        for (int i = 0; i < 4; i++) {
            int c = tid + i * 256;
            int row = c >> 3, kg = c & 7;
            u32 off = swzf((u32)(row * 128 + kg * 16));
            cpasync16(base + off,         Xh + (size_t)(m0 + row) * K + k0 + kg * 8);
            cpasync16(base + 16384 + off, Xl + (size_t)(m0 + row) * K + k0 + kg * 8);
        }
#pragma unroll
        for (int i = 0; i < 2; i++) {
            int c = tid + i * 256;
            int row = c >> 3, kg = c & 7;
            u32 off = swzf((u32)(row * 128 + kg * 16));
            cpasync16(base + 32768 + off, Wh + (size_t)(n0 + row) * K + k0 + kg * 8);
        }
        CP_COMMIT();
    };

    issue(0);

    for (int t = 0; t < nIter; t++) {
        CP_WAIT0();
        __syncthreads();
        if (t + 1 < nIter) issue(t + 1);

        u32 base = sb + (t & 1) * GH_BUF;
#pragma unroll
        for (int q = 0; q < 4; q++) {
            u32 ah[4], al[4];
            u32 aoff = swzf((u32)(arow * 128 + q * 32 + akh * 16));
            ldsm4(ah, base + aoff);
            ldsm4(al, base + 16384 + aoff);
            const int bchunk = 2 * q + (sub & 1);
            u32 bh[16];
#pragma unroll
            for (int g = 0; g < 4; g++) {
                u32 off = swzf((u32)((g * 16 + brow) * 128 + bchunk * 16));
                ldsm4(bh + g * 4, base + 32768 + off);
            }
#pragma unroll
            for (int g = 0; g < 4; g++) {
#pragma unroll
                for (int m = 0; m < 2; m++) {
                    int ng = g * 2 + m;
                    u32 b0 = bh[g * 4 + 2 * m], b1 = bh[g * 4 + 2 * m + 1];
                    mmaf16(acc[ng], ah, b0, b1);
                    mmaf16(acc[ng], al, b0, b1);
                }
            }
        }
        if (t + 1 < nIter) __syncthreads();
    }

    const int r0 = w * 16 + (l >> 2);
    const int r1 = r0 + 8;

    // ---- epilogue 1: attention scores ----
    {
        float s0 = 0.f, d0 = 0.f, s1 = 0.f, d1 = 0.f;
#pragma unroll
        for (int ng = 0; ng < 8; ng++) {
            int col = ng * 8 + 2 * (l & 3);
            float2 av = *(const float2*)(a_src + n0 + col);
            float2 dv = *(const float2*)(a_dst + n0 + col);
            s0 += acc[ng][0] * av.x + acc[ng][1] * av.y;
            d0 += acc[ng][0] * dv.x + acc[ng][1] * dv.y;
            s1 += acc[ng][2] * av.x + acc[ng][3] * av.y;
            d1 += acc[ng][2] * dv.x + acc[ng][3] * dv.y;
        }
        s0 += __shfl_xor_sync(0xffffffffu, s0, 1);
        s0 += __shfl_xor_sync(0xffffffffu, s0, 2);
        d0 += __shfl_xor_sync(0xffffffffu, d0, 1);
        d0 += __shfl_xor_sync(0xffffffffu, d0, 2);
        s1 += __shfl_xor_sync(0xffffffffu, s1, 1);
        s1 += __shfl_xor_sync(0xffffffffu, s1, 2);
        d1 += __shfl_xor_sync(0xffffffffu, d1, 1);
        d1 += __shfl_xor_sync(0xffffffffu, d1, 2);
        if ((l & 3) == 0) {
            int idx0 = h * (BATCH * NT) + m0 + r0;
            int idx1 = h * (BATCH * NT) + m0 + r1;
            s16[idx0] = __float2half_rn(s0);
            e16[idx0] = __float2half_rn(__expf(s0));
            f16[idx0] = __float2half_rn(__expf(0.2f * s0));
            dpk[idx0] = make_float4(d0, __expf(d0), __expf(0.2f * d0), 0.f);
            s16[idx1] = __float2half_rn(s1);
            e16[idx1] = __float2half_rn(__expf(s1));
            f16[idx1] = __float2half_rn(__expf(0.2f * s1));
            dpk[idx1] = make_float4(d1, __expf(d1), __expf(0.2f * d1), 0.f);
        }
    }

    // ---- epilogue 2: fp16 transpose via smem bounce ----
    __syncthreads();
    unsigned short* Th = (unsigned short*)smem;
#pragma unroll
    for (int ng = 0; ng < 8; ng++) {
        int col = ng * 8 + 2 * (l & 3);
#pragma unroll
        for (int v = 0; v < 4; v++) {
            int cc = col + (v & 1);
            int node = (v < 2) ? r0 : r1;
            u32 p = packh2(acc[ng][v], 0.f);
            Th[cc * TPAD + node] = (unsigned short)(p & 0xffffu);
        }
    }
    __syncthreads();

    const int b = m0 >> 10;
    const int node0 = m0 & (NT - 1);
    const size_t gbase = ((size_t)((h * BATCH + b) * 64)) * NT + node0;
    {
        int c = tid >> 2;
#pragma unroll
        for (int i = 0; i < 4; i++) {
            int nch = (tid & 3) + 4 * i;
            uint4 vh = *(const uint4*)(Th + c * TPAD + nch * 8);
            *(uint4*)(hT + gbase + (size_t)c * NT + nch * 8) = vh;
        }
    }
}

// ---------------- HMMA aggregation (fp16, half2 E-construction) ------------
__global__ __launch_bounds__(256, 2) void agg_mma_kernel(
    const __half* __restrict__ hTA,
    const __half* __restrict__ s16A, const __half* __restrict__ e16A,
    const __half* __restrict__ f16A, const float4* __restrict__ dpkA,
    const ull* __restrict__ bits64,
    const float* __restrict__ bias,
    __half* __restrict__ xhi, __half* __restrict__ xlo,
    float* __restrict__ xoutf, int wf32, int H)
{
    __shared__ __align__(16) __half sh_h[2][64 * 64];
    __shared__ __align__(16) u32 sh_s[2][96];     // [buf][s(32) | Es(32) | F(32)]

    const int tid = threadIdx.x;
    const int w = tid >> 5, l = tid & 31;
    const int b = blockIdx.z, h = blockIdx.y;
    const int i0 = blockIdx.x * 128;
    const int hb = h * BATCH + b;
    const int fs = H * 64;

    const int r0 = w * 16 + (l >> 2);
    const int r1 = r0 + 8;
    const float4 dp0 = dpkA[hb * NT + i0 + r0];
    const float4 dp1 = dpkA[hb * NT + i0 + r1];
    // half2 broadcast constants for the two rows
    const u32 dd0h = packh2(dp0.x, dp0.x), Ed0h = packh2(dp0.y, dp0.y), Fd0h = packh2(dp0.z, dp0.z);
    const u32 dd1h = packh2(dp1.x, dp1.x), Ed1h = packh2(dp1.y, dp1.y), Fd1h = packh2(dp1.z, dp1.z);
    const u32 ndd0h = dd0h ^ 0x80008000u;   // -d, for s > -d compare
    const u32 ndd1h = dd1h ^ 0x80008000u;
    const ull* mrow0 = bits64 + (size_t)(b * NT + i0 + r0) * 16;
    const ull* mrow1 = bits64 + (size_t)(b * NT + i0 + r1) * 16;

    const __half* hhp = hTA + (size_t)hb * 64 * NT;
    // score plane pointer for this thread's staging role
    const u32* scp = (tid < 32) ? (const u32*)(s16A + hb * NT)
                   : (tid < 64) ? (const u32*)(e16A + hb * NT)
                                : (const u32*)(f16A + hb * NT);

    const int c0 = tid >> 3, jc = tid & 7;
    const u32 st0 = swzf((u32)(c0 * 128 + jc * 16));
    const u32 st1 = swzf((u32)((c0 + 32) * 128 + jc * 16));

    float acc[8][4];
#pragma unroll
    for (int ng = 0; ng < 8; ng++)
#pragma unroll
        for (int r = 0; r < 4; r++) acc[ng][r] = 0.f;
    float accrs[4] = {0.f, 0.f, 0.f, 0.f};

    uint4 pvh0, pvh1;
    u32 pscu = 0;

    auto ldg_tile = [&](int t) {
        int j0 = t * 64;
        pvh0 = *(const uint4*)(hhp + (size_t)c0 * NT + j0 + jc * 8);
        pvh1 = *(const uint4*)(hhp + (size_t)(c0 + 32) * NT + j0 + jc * 8);
        if (tid < 96) pscu = scp[(j0 >> 1) + (tid & 31)];
    };

    ldg_tile(0);

    const u32 su[2] = { smem_u32(sh_h[0]), smem_u32(sh_h[1]) };

    const int sub = l >> 3;
    const int brow = (l & 7) + ((sub >> 1) << 3);
    const int jq = l & 3;   // jA = q*16 + 2*jq

    for (int t = 0; t < 16; t++) {
        int buf = t & 1;
        *(uint4*)((char*)sh_h[buf] + st0) = pvh0;
        *(uint4*)((char*)sh_h[buf] + st1) = pvh1;
        if (tid < 96) sh_s[buf][tid] = pscu;
        __syncthreads();
        if (t < 15) ldg_tile(t + 1);

        const u32* sS = sh_s[buf];
        const u32* sE = sh_s[buf] + 32;
        const u32* sF = sh_s[buf] + 64;
        const ull m0 = mrow0[t];
        const ull m1 = mrow1[t];

#pragma unroll
        for (int q = 0; q < 4; q++) {
            const int jA = q * 16 + 2 * jq;
            const int jw = q * 8 + jq;
            u32 s01 = sS[jw],     s89 = sS[jw + 4];
            u32 E01 = sE[jw],     E89 = sE[jw + 4];
            u32 F01 = sF[jw],     F89 = sF[jw + 4];

            u32 ahi[4];
            // row r0: e = (s > -d) ? Es*Ed : Es2*Ed2, masked by adjacency
            {
                u32 c1 = h2gtmask(s01, ndd0h);
                u32 c2 = h2gtmask(s89, ndd0h);
                u32 a1 = h2mul(E01, Ed0h), b1 = h2mul(F01, Fd0h);
                u32 a2 = h2mul(E89, Ed0h), b2 = h2mul(F89, Fd0h);
                ahi[0] = ((a1 & c1) | (b1 & ~c1)) & mask2((u32)(m0 >> jA));
                ahi[2] = ((a2 & c2) | (b2 & ~c2)) & mask2((u32)(m0 >> (jA + 8)));
            }
            // row r1
            {
                u32 c1 = h2gtmask(s01, ndd1h);
                u32 c2 = h2gtmask(s89, ndd1h);
                u32 a1 = h2mul(E01, Ed1h), b1 = h2mul(F01, Fd1h);
                u32 a2 = h2mul(E89, Ed1h), b2 = h2mul(F89, Fd1h);
                ahi[1] = ((a1 & c1) | (b1 & ~c1)) & mask2((u32)(m1 >> jA));
                ahi[3] = ((a2 & c2) | (b2 & ~c2)) & mask2((u32)(m1 >> (jA + 8)));
            }

            // rowsum of the packed weights via ones-B MMA (exact cancellation)
            mmaf16(accrs, ahi, ONESH, ONESH);

            u32 bh[16];
            const int bchunk = 2 * q + (sub & 1);
#pragma unroll
            for (int g = 0; g < 4; g++) {
                u32 off = swzf((u32)((g * 16 + brow) * 128 + bchunk * 16));
                ldsm4(bh + g * 4, su[buf] + off);
            }
#pragma unroll
            for (int g = 0; g < 4; g++) {
#pragma unroll
                for (int m = 0; m < 2; m++) {
                    int ng = g * 2 + m;
                    mmaf16(acc[ng], ahi, bh[g * 4 + 2 * m], bh[g * 4 + 2 * m + 1]);
                }
            }
        }
        if (t < 15) __syncthreads();
    }

    float rinv0 = 1.0f / accrs[0];
    float rinv1 = 1.0f / accrs[2];

    const size_t ro0 = (size_t)(b * NT + i0 + r0) * fs + h * 64;
    const size_t ro1 = (size_t)(b * NT + i0 + r1) * fs + h * 64;
#pragma unroll
    for (int ng = 0; ng < 8; ng++) {
        int col = ng * 8 + 2 * (l & 3);
        float2 bb = *(const float2*)(bias + h * 64 + col);
        float2 o0, o1;
        o0.x = fmaxf(acc[ng][0] * rinv0 + bb.x, 0.f);
        o0.y = fmaxf(acc[ng][1] * rinv0 + bb.y, 0.f);
        o1.x = fmaxf(acc[ng][2] * rinv1 + bb.x, 0.f);
        o1.y = fmaxf(acc[ng][3] * rinv1 + bb.y, 0.f);
        if (wf32) {
            *(float2*)(xoutf + ro0 + col) = o0;
            *(float2*)(xoutf + ro1 + col) = o1;
        } else {
            u32 ph, pl;
            split2h(o0.x, o0.y, ph, pl);
            *(u32*)(xhi + ro0 + col) = ph;
            *(u32*)(xlo + ro0 + col) = pl;
            split2h(o1.x, o1.y, ph, pl);
            *(u32*)(xhi + ro1 + col) = ph;
            *(u32*)(xlo + ro1 + col) = pl;
        }
    }
}

// ---------------- readout: gsum + z2 fused (one block per batch) -----------
__global__ __launch_bounds__(256) void gz_kernel(
    const float* __restrict__ x, const float* __restrict__ wg,
    const float* __restrict__ bg, const float* __restrict__ wv,
    float* __restrict__ z2)
{
    int b = blockIdx.x;
    int tid = threadIdx.x;
    int c = tid & 63, nq = tid >> 6;
    float acc = 0.f;
    for (int n = nq; n < NT; n += 4) acc += x[((size_t)b * NT + n) * 64 + c];
    __shared__ float sm[256];
    __shared__ float g[64];
    sm[tid] = acc;
    __syncthreads();
    if (tid < 64) g[tid] = sm[tid] + sm[64 + tid] + sm[128 + tid] + sm[192 + tid];
    __syncthreads();
    float y = 0.f;
    if (tid < 64) {
        float a2 = bg[tid];
        for (int k = 0; k < 64; k++) a2 += g[k] * wg[tid * 64 + k];
        y = fmaxf(a2, 0.f) * wv[64 + tid];
    }
    sm[tid] = y;
    __syncthreads();
    if (tid == 0) {
        float t = 0.f;
        for (int k = 0; k < 64; k++) t += sm[k];
        z2[b] = t;
    }
}

__global__ __launch_bounds__(256) void final_kernel(
    const float* __restrict__ x,
    const float* __restrict__ wn, const float* __restrict__ bn,
    const float* __restrict__ wv, const float* __restrict__ bv,
    const float* __restrict__ z2, float* __restrict__ out)
{
    __shared__ float wns[64][65];
    __shared__ float bns[64], wvs[64];
    int tid = threadIdx.x;
#pragma unroll
    for (int l = 0; l < 16; l++) {
        int f = tid + l * 256;
        wns[f >> 6][f & 63] = wn[f];
    }
    if (tid < 64) { bns[tid] = bn[tid]; wvs[tid] = wv[tid]; }
    __syncthreads();

    int row = blockIdx.x * 64 + (tid >> 2);
    int q = tid & 3;
    float xr[64];
#pragma unroll
    for (int k = 0; k < 64; k++) xr[k] = x[(size_t)row * 64 + k];
    float y = 0.f;
    for (int c16 = 0; c16 < 16; c16++) {
        int c = q * 16 + c16;
        float acc = bns[c];
#pragma unroll
        for (int k = 0; k < 64; k++) acc += xr[k] * wns[c][k];
        y += fmaxf(acc, 0.f) * wvs[c];
    }
    y += __shfl_xor_sync(0xffffffffu, y, 1);
    y += __shfl_xor_sync(0xffffffffu, y, 2);
    if (q == 0) out[row] = y + z2[row >> 10] + bv[0];
}

// ---------------- launch ----------------------------------------------------
extern "C" void kernel_launch(void* const* d_in, const int* in_sizes, int n_in,
                              void* d_out, int out_size)
{
    const float* xin = (const float*)d_in[0];
    const int*   adj = (const int*)d_in[1];
    const float* w1  = (const float*)d_in[2];
    const float* as1 = (const float*)d_in[3];
    const float* ad1 = (const float*)d_in[4];
    const float* b1  = (const float*)d_in[5];
    const float* w2  = (const float*)d_in[6];
    const float* as2 = (const float*)d_in[7];
    const float* ad2 = (const float*)d_in[8];
    const float* b2  = (const float*)d_in[9];
    const float* w3  = (const float*)d_in[10];
    const float* as3 = (const float*)d_in[11];
    const float* ad3 = (const float*)d_in[12];
    const float* b3  = (const float*)d_in[13];
    const float* wn  = (const float*)d_in[14];
    const float* bn  = (const float*)d_in[15];
    const float* wg  = (const float*)d_in[16];
    const float* bg  = (const float*)d_in[17];
    const float* wv  = (const float*)d_in[18];
    const float* bv  = (const float*)d_in[19];
    float* out = (float*)d_out;

    float *bufB, *z2p;
    float4* dpk;
    __half *hT, *xhi, *xlo, *w1h, *w2h, *w3h, *s16, *e16, *f16;
    u32* bits;
    cudaGetSymbolAddress((void**)&bufB, g_bufB);
    cudaGetSymbolAddress((void**)&dpk,  g_dpk);
    cudaGetSymbolAddress((void**)&hT,   g_hT);
    cudaGetSymbolAddress((void**)&xhi,  g_xhi);
    cudaGetSymbolAddress((void**)&xlo,  g_xlo);
    cudaGetSymbolAddress((void**)&w1h,  g_w1h);
    cudaGetSymbolAddress((void**)&w2h,  g_w2h);
    cudaGetSymbolAddress((void**)&w3h,  g_w3h);
    cudaGetSymbolAddress((void**)&s16,  g_s16);
    cudaGetSymbolAddress((void**)&e16,  g_e16);
    cudaGetSymbolAddress((void**)&f16,  g_f16);
    cudaGetSymbolAddress((void**)&bits, g_bits);
    cudaGetSymbolAddress((void**)&z2p,  g_z2);

    cudaFuncSetAttribute(gemm_h16, cudaFuncAttributeMaxDynamicSharedMemorySize, GH_SMEM);

    const int M = BATCH * NT;
    const ull* bits64 = (const ull*)bits;

    prep_all_kernel<<<1632, 256>>>(adj, bits, xin, w1, w2, w3,
                                   xhi, xlo, w1h, w2h, w3h);

    // layer 1: 64 -> 4x64
    gemm_h16<<<dim3(M / 128, 4), 256, GH_SMEM>>>(xhi, xlo, w1h, as1, ad1,
                                                 s16, e16, f16, dpk, hT, 64);
    agg_mma_kernel<<<dim3(NT / 128, 4, BATCH), 256>>>(
        hT, s16, e16, f16, dpk, bits64, b1, xhi, xlo, nullptr, 0, 4);

    // layer 2: 4x64 -> 4x64
    gemm_h16<<<dim3(M / 128, 4), 256, GH_SMEM>>>(xhi, xlo, w2h, as2, ad2,
                                                 s16, e16, f16, dpk, hT, 256);
    agg_mma_kernel<<<dim3(NT / 128, 4, BATCH), 256>>>(
        hT, s16, e16, f16, dpk, bits64, b2, xhi, xlo, nullptr, 0, 4);

    // layer 3: 4x64 -> 64 (H=1)
    gemm_h16<<<dim3(M / 128, 1), 256, GH_SMEM>>>(xhi, xlo, w3h, as3, ad3,
                                                 s16, e16, f16, dpk, hT, 256);
    agg_mma_kernel<<<dim3(NT / 128, 1, BATCH), 256>>>(
        hT, s16, e16, f16, dpk, bits64, b3, nullptr, nullptr, bufB, 1, 1);

    // readout
    gz_kernel<<<BATCH, 256>>>(bufB, wg, bg, wv, z2p);
    final_kernel<<<M / 64, 256>>>(bufB, wn, bn, wv, bv, z2p, out);
}